// round 1
// baseline (speedup 1.0000x reference)
#include <cuda_runtime.h>
#include <cuda_bf16.h>

#define B_ 8
#define N_ 1024
#define C_ 256
#define HD_ 256   // H*D
#define NEG_SLOPE 0.2f

// Scratch (no cudaMalloc allowed)
__device__ float g_Wx[B_ * N_ * HD_];      // 8M floats = 32MB
__device__ float g_ei[B_ * N_ * 4];
__device__ float g_ej[B_ * N_ * 4];

// ---------------------------------------------------------------------------
// Kernel 1: Wx = x @ W     (M=8192, K=256, N=256), 64x64 tile, 256 threads
// ---------------------------------------------------------------------------
__global__ void gemm_kernel(const float* __restrict__ A,
                            const float* __restrict__ Bm,
                            float* __restrict__ Cm) {
    __shared__ float As[16][64 + 1];   // [k][m]
    __shared__ float Bs[16][64];       // [k][n]

    const int tid = threadIdx.x;
    const int tx = tid & 15;           // 16 col groups
    const int ty = tid >> 4;           // 16 row groups
    const int rowBase = blockIdx.x * 64;
    const int colBase = blockIdx.y * 64;

    float acc[4][4];
#pragma unroll
    for (int i = 0; i < 4; i++)
#pragma unroll
        for (int j = 0; j < 4; j++) acc[i][j] = 0.f;

    for (int kb = 0; kb < C_; kb += 16) {
        // load A tile 64x16
#pragma unroll
        for (int i = tid; i < 64 * 16; i += 256) {
            int r = i >> 4, c = i & 15;
            As[c][r] = A[(size_t)(rowBase + r) * C_ + kb + c];
        }
        // load B tile 16x64
#pragma unroll
        for (int i = tid; i < 16 * 64; i += 256) {
            int r = i >> 6, c = i & 63;
            Bs[r][c] = Bm[(size_t)(kb + r) * HD_ + colBase + c];
        }
        __syncthreads();
#pragma unroll
        for (int k = 0; k < 16; k++) {
            float av[4], bv[4];
#pragma unroll
            for (int i = 0; i < 4; i++) av[i] = As[k][ty * 4 + i];
#pragma unroll
            for (int j = 0; j < 4; j++) bv[j] = Bs[k][tx * 4 + j];
#pragma unroll
            for (int i = 0; i < 4; i++)
#pragma unroll
                for (int j = 0; j < 4; j++) acc[i][j] += av[i] * bv[j];
        }
        __syncthreads();
    }
#pragma unroll
    for (int i = 0; i < 4; i++)
#pragma unroll
        for (int j = 0; j < 4; j++)
            Cm[(size_t)(rowBase + ty * 4 + i) * HD_ + colBase + tx * 4 + j] = acc[i][j];
}

// ---------------------------------------------------------------------------
// Kernel 2: e_i/e_j projections.  One block per (b,n) row, 256 threads.
// ---------------------------------------------------------------------------
__global__ void eij_kernel(const float* __restrict__ a,
                           const float* __restrict__ Wx,
                           float* __restrict__ ei, float* __restrict__ ej) {
    const int row = blockIdx.x;
    const int t = threadIdx.x;
    const int h = t >> 6, d = t & 63;

    float wx = Wx[(size_t)row * HD_ + t];
    float vi = wx * a[h * 128 + d];
    float vj = wx * a[h * 128 + 64 + d];

    __shared__ float si[256], sj[256];
    si[t] = vi; sj[t] = vj;
    __syncthreads();
#pragma unroll
    for (int s = 32; s > 0; s >>= 1) {
        if (d < s) { si[t] += si[t + s]; sj[t] += sj[t + s]; }
        __syncthreads();
    }
    if (d == 0) {
        ei[row * 4 + h] = si[t];
        ej[row * 4 + h] = sj[t];
    }
}

// ---------------------------------------------------------------------------
// Kernel 3: sparse-compact softmax + aggregation.  Block per (b,n).
// ---------------------------------------------------------------------------
__global__ void __launch_bounds__(256)
gat_kernel(const float* __restrict__ adj,
           const float* __restrict__ Wx,
           const float* __restrict__ ei,
           const float* __restrict__ ej,
           float* __restrict__ out) {
    const int b = blockIdx.x >> 10;
    const int n = blockIdx.x & 1023;
    const int t = threadIdx.x;

    __shared__ unsigned short s_idx[N_];
    __shared__ float s_e[N_ * 4];      // per-neighbor e for 4 heads
    __shared__ float s_red[256 * 4];
    __shared__ int s_warp[8];
    __shared__ int s_off[9];

    const float* adj_row = adj + ((size_t)(b * N_ + n)) * N_;

    // --- deterministic compaction of nonzero neighbors (incl. self) ---
    bool p[4];
    int cnt = 0;
    const int jb = t * 4;
#pragma unroll
    for (int i = 0; i < 4; i++) {
        int j = jb + i;
        float av = adj_row[j];
        p[i] = (av != 0.f) || (j == n);
        cnt += p[i] ? 1 : 0;
    }
    const int lane = t & 31, w = t >> 5;
    int x = cnt;
#pragma unroll
    for (int o = 1; o < 32; o <<= 1) {
        int y = __shfl_up_sync(0xffffffffu, x, o);
        if (lane >= o) x += y;
    }
    if (lane == 31) s_warp[w] = x;
    __syncthreads();
    if (t == 0) {
        int s = 0;
#pragma unroll
        for (int i = 0; i < 8; i++) { s_off[i] = s; s += s_warp[i]; }
        s_off[8] = s;
    }
    __syncthreads();
    int pos = s_off[w] + x - cnt;
#pragma unroll
    for (int i = 0; i < 4; i++) {
        if (p[i]) s_idx[pos++] = (unsigned short)(jb + i);
    }
    const int nnz = s_off[8];
    __syncthreads();

    // --- e = leaky_relu(ei[n] + ej[j]) for compacted j ---
    float4 ei4 = *(const float4*)(ei + (size_t)(b * N_ + n) * 4);
    for (int k = t; k < nnz; k += 256) {
        int j = s_idx[k];
        float4 e4 = *(const float4*)(ej + (size_t)(b * N_ + j) * 4);
        e4.x += ei4.x; e4.y += ei4.y; e4.z += ei4.z; e4.w += ei4.w;
        e4.x = e4.x > 0.f ? e4.x : NEG_SLOPE * e4.x;
        e4.y = e4.y > 0.f ? e4.y : NEG_SLOPE * e4.y;
        e4.z = e4.z > 0.f ? e4.z : NEG_SLOPE * e4.z;
        e4.w = e4.w > 0.f ? e4.w : NEG_SLOPE * e4.w;
        ((float4*)s_e)[k] = e4;
    }
    __syncthreads();

    // --- max over neighbors, per head ---
    float4 m4 = make_float4(-1e30f, -1e30f, -1e30f, -1e30f);
    for (int k = t; k < nnz; k += 256) {
        float4 v = ((float4*)s_e)[k];
        m4.x = fmaxf(m4.x, v.x); m4.y = fmaxf(m4.y, v.y);
        m4.z = fmaxf(m4.z, v.z); m4.w = fmaxf(m4.w, v.w);
    }
    ((float4*)s_red)[t] = m4;
    __syncthreads();
#pragma unroll
    for (int s = 128; s > 0; s >>= 1) {
        if (t < s) {
            float4 a4 = ((float4*)s_red)[t];
            float4 b4 = ((float4*)s_red)[t + s];
            a4.x = fmaxf(a4.x, b4.x); a4.y = fmaxf(a4.y, b4.y);
            a4.z = fmaxf(a4.z, b4.z); a4.w = fmaxf(a4.w, b4.w);
            ((float4*)s_red)[t] = a4;
        }
        __syncthreads();
    }
    float4 mx = ((float4*)s_red)[0];
    __syncthreads();

    // --- exp + sum ---
    float4 t4 = make_float4(0.f, 0.f, 0.f, 0.f);
    for (int k = t; k < nnz; k += 256) {
        float4 v = ((float4*)s_e)[k];
        v.x = __expf(v.x - mx.x); v.y = __expf(v.y - mx.y);
        v.z = __expf(v.z - mx.z); v.w = __expf(v.w - mx.w);
        t4.x += v.x; t4.y += v.y; t4.z += v.z; t4.w += v.w;
        ((float4*)s_e)[k] = v;
    }
    ((float4*)s_red)[t] = t4;
    __syncthreads();
#pragma unroll
    for (int s = 128; s > 0; s >>= 1) {
        if (t < s) {
            float4 a4 = ((float4*)s_red)[t];
            float4 b4 = ((float4*)s_red)[t + s];
            a4.x += b4.x; a4.y += b4.y; a4.z += b4.z; a4.w += b4.w;
            ((float4*)s_red)[t] = a4;
        }
        __syncthreads();
    }
    float4 sm = ((float4*)s_red)[0];

    // --- aggregation: thread t owns output column t = h*64+d ---
    const int h = t >> 6;
    float sum_h = (h == 0) ? sm.x : (h == 1) ? sm.y : (h == 2) ? sm.z : sm.w;
    float rs = 1.f / sum_h;
    float acc = 0.f;
    const float* WxB = Wx + (size_t)b * N_ * HD_ + t;
#pragma unroll 4
    for (int k = 0; k < nnz; k++) {
        int j = s_idx[k];
        acc += s_e[k * 4 + h] * WxB[(size_t)j * HD_];
    }
    out[(size_t)(b * N_ + n) * HD_ + t] = acc * rs;
}

// ---------------------------------------------------------------------------
extern "C" void kernel_launch(void* const* d_in, const int* in_sizes, int n_in,
                              void* d_out, int out_size) {
    const float* x   = (const float*)d_in[0];   // (8,1024,256)
    const float* adj = (const float*)d_in[1];   // (8,1024,1024)
    const float* W   = (const float*)d_in[2];   // (256,256)
    const float* a   = (const float*)d_in[3];   // (1,4,128)
    float* out = (float*)d_out;

    float* Wx; cudaGetSymbolAddress((void**)&Wx, g_Wx);
    float* ei; cudaGetSymbolAddress((void**)&ei, g_ei);
    float* ej; cudaGetSymbolAddress((void**)&ej, g_ej);

    dim3 ggrid(B_ * N_ / 64, HD_ / 64);
    gemm_kernel<<<ggrid, 256>>>(x, W, Wx);
    eij_kernel<<<B_ * N_, 256>>>(a, Wx, ei, ej);
    gat_kernel<<<B_ * N_, 256>>>(adj, Wx, ei, ej, out);
}

// round 2
// speedup vs baseline: 1.5973x; 1.5973x over previous
#include <cuda_runtime.h>
#include <cuda_bf16.h>

#define B_ 8
#define N_ 1024
#define C_ 256
#define HD_ 256   // H*D
#define NEG_SLOPE 0.2f

// Scratch (no cudaMalloc allowed)
__device__ float g_Wx[B_ * N_ * HD_];      // 32MB
__device__ float g_ei[B_ * N_ * 4];
__device__ float g_ej[B_ * N_ * 4];

// ---------------------------------------------------------------------------
// Kernel 1: Wx = x @ W   (M=8192, K=256, N=256)
// BM=128, BN=64, BK=32, 256 threads, TM=8, TN=4
// ---------------------------------------------------------------------------
__global__ void __launch_bounds__(256)
gemm_kernel(const float* __restrict__ A,
            const float* __restrict__ Bm,
            float* __restrict__ Cm) {
    __shared__ float As[128][33];   // [m][k], pad 1 -> conflict-free
    __shared__ float Bs[32][64];    // [k][n]

    const int tid = threadIdx.x;
    const int rowBase = blockIdx.x * 128;
    const int colBase = blockIdx.y * 64;

    const int tx = tid & 15;        // 16 col groups * TN=4 -> 64
    const int ty = tid >> 4;        // 16 row groups * TM=8 -> 128

    // A-load assignment: r0 = tid>>3 (0..31), f = tid&7 -> cols f*4..f*4+3
    const int ar0 = tid >> 3;
    const int af  = tid & 7;
    // B-load assignment: kr = tid>>3 (0..31), f -> cols f*8..f*8+7
    const int bkr = tid >> 3;

    float acc[8][4];
#pragma unroll
    for (int i = 0; i < 8; i++)
#pragma unroll
        for (int j = 0; j < 4; j++) acc[i][j] = 0.f;

    for (int kb = 0; kb < C_; kb += 32) {
        // load A tile 128x32 (4 float4 per thread, scalar smem stores)
#pragma unroll
        for (int i = 0; i < 4; i++) {
            int r = ar0 + 32 * i;
            float4 v = *(const float4*)(A + (size_t)(rowBase + r) * C_ + kb + af * 4);
            As[r][af * 4 + 0] = v.x;
            As[r][af * 4 + 1] = v.y;
            As[r][af * 4 + 2] = v.z;
            As[r][af * 4 + 3] = v.w;
        }
        // load B tile 32x64 (2 float4 per thread)
#pragma unroll
        for (int i = 0; i < 2; i++) {
            float4 v = *(const float4*)(Bm + (size_t)(kb + bkr) * HD_ + colBase + af * 8 + i * 4);
            *(float4*)(&Bs[bkr][af * 8 + i * 4]) = v;
        }
        __syncthreads();

#pragma unroll
        for (int k = 0; k < 32; k++) {
            float av[8];
#pragma unroll
            for (int i = 0; i < 8; i++) av[i] = As[ty * 8 + i][k];
            float4 bv = *(const float4*)(&Bs[k][tx * 4]);
#pragma unroll
            for (int i = 0; i < 8; i++) {
                acc[i][0] += av[i] * bv.x;
                acc[i][1] += av[i] * bv.y;
                acc[i][2] += av[i] * bv.z;
                acc[i][3] += av[i] * bv.w;
            }
        }
        __syncthreads();
    }
#pragma unroll
    for (int i = 0; i < 8; i++) {
        float4 v = make_float4(acc[i][0], acc[i][1], acc[i][2], acc[i][3]);
        *(float4*)(Cm + (size_t)(rowBase + ty * 8 + i) * HD_ + colBase + tx * 4) = v;
    }
}

// ---------------------------------------------------------------------------
// Kernel 2: e_i/e_j projections.  One block per (b,n) row, 256 threads.
// ---------------------------------------------------------------------------
__global__ void eij_kernel(const float* __restrict__ a,
                           const float* __restrict__ Wx,
                           float* __restrict__ ei, float* __restrict__ ej) {
    const int row = blockIdx.x;
    const int t = threadIdx.x;
    const int h = t >> 6, d = t & 63;

    float wx = Wx[(size_t)row * HD_ + t];
    float vi = wx * a[h * 128 + d];
    float vj = wx * a[h * 128 + 64 + d];

    // warp-level reduce (each head = 2 warps of 32)
    const int lane = t & 31;
#pragma unroll
    for (int o = 16; o > 0; o >>= 1) {
        vi += __shfl_xor_sync(0xffffffffu, vi, o);
        vj += __shfl_xor_sync(0xffffffffu, vj, o);
    }
    __shared__ float si[8], sj[8];
    const int w = t >> 5;
    if (lane == 0) { si[w] = vi; sj[w] = vj; }
    __syncthreads();
    if (t < 4) {
        ei[row * 4 + t] = si[t * 2] + si[t * 2 + 1];
        ej[row * 4 + t] = sj[t * 2] + sj[t * 2 + 1];
    }
}

// ---------------------------------------------------------------------------
// Kernel 3: sparse-compact softmax + aggregation.  Block per (b,n).
// ---------------------------------------------------------------------------
__global__ void __launch_bounds__(256)
gat_kernel(const float* __restrict__ adj,
           const float* __restrict__ Wx,
           const float* __restrict__ ei,
           const float* __restrict__ ej,
           float* __restrict__ out) {
    const int b = blockIdx.x >> 10;
    const int n = blockIdx.x & 1023;
    const int t = threadIdx.x;
    const int lane = t & 31, w = t >> 5;

    __shared__ unsigned short s_idx[N_];
    __shared__ float s_e[N_ * 4];          // per-neighbor e for 4 heads
    __shared__ float s_red[256 * 4];       // group partials (float4 view)
    __shared__ int   s_warp[8];
    __shared__ int   s_off[9];
    __shared__ float4 s_wred[8];
    __shared__ float4 s_bcast;

    const float* adj_row = adj + ((size_t)(b * N_ + n)) * N_;

    // --- deterministic compaction of nonzero neighbors (incl. self) ---
    const int jb = t * 4;
    float4 av4 = *(const float4*)(adj_row + jb);
    bool p[4];
    p[0] = (av4.x != 0.f) || (jb + 0 == n);
    p[1] = (av4.y != 0.f) || (jb + 1 == n);
    p[2] = (av4.z != 0.f) || (jb + 2 == n);
    p[3] = (av4.w != 0.f) || (jb + 3 == n);
    int cnt = (p[0] ? 1 : 0) + (p[1] ? 1 : 0) + (p[2] ? 1 : 0) + (p[3] ? 1 : 0);

    int x = cnt;
#pragma unroll
    for (int o = 1; o < 32; o <<= 1) {
        int y = __shfl_up_sync(0xffffffffu, x, o);
        if (lane >= o) x += y;
    }
    if (lane == 31) s_warp[w] = x;
    __syncthreads();
    if (t == 0) {
        int s = 0;
#pragma unroll
        for (int i = 0; i < 8; i++) { s_off[i] = s; s += s_warp[i]; }
        s_off[8] = s;
    }
    __syncthreads();
    int pos = s_off[w] + x - cnt;
#pragma unroll
    for (int i = 0; i < 4; i++) {
        if (p[i]) s_idx[pos++] = (unsigned short)(jb + i);
    }
    const int nnz = s_off[8];
    __syncthreads();

    // --- e = leaky_relu(ei[n] + ej[j]) for compacted j ---
    float4 ei4 = *(const float4*)(ei + (size_t)(b * N_ + n) * 4);
    for (int k = t; k < nnz; k += 256) {
        int j = s_idx[k];
        float4 e4 = *(const float4*)(ej + (size_t)(b * N_ + j) * 4);
        e4.x += ei4.x; e4.y += ei4.y; e4.z += ei4.z; e4.w += ei4.w;
        e4.x = e4.x > 0.f ? e4.x : NEG_SLOPE * e4.x;
        e4.y = e4.y > 0.f ? e4.y : NEG_SLOPE * e4.y;
        e4.z = e4.z > 0.f ? e4.z : NEG_SLOPE * e4.z;
        e4.w = e4.w > 0.f ? e4.w : NEG_SLOPE * e4.w;
        ((float4*)s_e)[k] = e4;
    }
    __syncthreads();

    // --- per-head max (warp shuffle reduction) ---
    float4 m4 = make_float4(-1e30f, -1e30f, -1e30f, -1e30f);
    for (int k = t; k < nnz; k += 256) {
        float4 v = ((float4*)s_e)[k];
        m4.x = fmaxf(m4.x, v.x); m4.y = fmaxf(m4.y, v.y);
        m4.z = fmaxf(m4.z, v.z); m4.w = fmaxf(m4.w, v.w);
    }
#pragma unroll
    for (int o = 16; o > 0; o >>= 1) {
        m4.x = fmaxf(m4.x, __shfl_xor_sync(0xffffffffu, m4.x, o));
        m4.y = fmaxf(m4.y, __shfl_xor_sync(0xffffffffu, m4.y, o));
        m4.z = fmaxf(m4.z, __shfl_xor_sync(0xffffffffu, m4.z, o));
        m4.w = fmaxf(m4.w, __shfl_xor_sync(0xffffffffu, m4.w, o));
    }
    if (lane == 0) s_wred[w] = m4;
    __syncthreads();
    if (t == 0) {
        float4 r = s_wred[0];
#pragma unroll
        for (int i = 1; i < 8; i++) {
            float4 v = s_wred[i];
            r.x = fmaxf(r.x, v.x); r.y = fmaxf(r.y, v.y);
            r.z = fmaxf(r.z, v.z); r.w = fmaxf(r.w, v.w);
        }
        s_bcast = r;
    }
    __syncthreads();
    float4 mx = s_bcast;

    // --- exp + per-head sum ---
    float4 t4 = make_float4(0.f, 0.f, 0.f, 0.f);
    for (int k = t; k < nnz; k += 256) {
        float4 v = ((float4*)s_e)[k];
        v.x = __expf(v.x - mx.x); v.y = __expf(v.y - mx.y);
        v.z = __expf(v.z - mx.z); v.w = __expf(v.w - mx.w);
        t4.x += v.x; t4.y += v.y; t4.z += v.z; t4.w += v.w;
        ((float4*)s_e)[k] = v;
    }
#pragma unroll
    for (int o = 16; o > 0; o >>= 1) {
        t4.x += __shfl_xor_sync(0xffffffffu, t4.x, o);
        t4.y += __shfl_xor_sync(0xffffffffu, t4.y, o);
        t4.z += __shfl_xor_sync(0xffffffffu, t4.z, o);
        t4.w += __shfl_xor_sync(0xffffffffu, t4.w, o);
    }
    if (lane == 0) s_wred[w] = t4;
    __syncthreads();
    if (t == 0) {
        float4 r = s_wred[0];
#pragma unroll
        for (int i = 1; i < 8; i++) {
            float4 v = s_wred[i];
            r.x += v.x; r.y += v.y; r.z += v.z; r.w += v.w;
        }
        s_bcast = r;
    }
    __syncthreads();
    float4 sm = s_bcast;

    // --- aggregation: 4 neighbor-groups x 64 threads, float4 columns ---
    const int g = t >> 6;        // neighbor stride group 0..3
    const int q = t & 63;        // column quad 0..63 (cols q*4..q*4+3)
    const int h = q >> 4;        // head of these 4 columns
    float4 acc = make_float4(0.f, 0.f, 0.f, 0.f);
    const float* WxB = Wx + (size_t)b * N_ * HD_ + q * 4;
#pragma unroll 4
    for (int k = g; k < nnz; k += 4) {
        int j = s_idx[k];
        float c = s_e[k * 4 + h];
        float4 wv = *(const float4*)(WxB + (size_t)j * HD_);
        acc.x += c * wv.x; acc.y += c * wv.y;
        acc.z += c * wv.z; acc.w += c * wv.w;
    }
    ((float4*)s_red)[t] = acc;
    __syncthreads();
    if (t < 64) {
        float4 a0 = ((float4*)s_red)[t];
        float4 a1 = ((float4*)s_red)[64 + t];
        float4 a2 = ((float4*)s_red)[128 + t];
        float4 a3 = ((float4*)s_red)[192 + t];
        const int hh = t >> 4;
        float sum_h = (hh == 0) ? sm.x : (hh == 1) ? sm.y : (hh == 2) ? sm.z : sm.w;
        float rs = 1.f / sum_h;
        float4 o;
        o.x = (a0.x + a1.x + a2.x + a3.x) * rs;
        o.y = (a0.y + a1.y + a2.y + a3.y) * rs;
        o.z = (a0.z + a1.z + a2.z + a3.z) * rs;
        o.w = (a0.w + a1.w + a2.w + a3.w) * rs;
        ((float4*)(out + (size_t)(b * N_ + n) * HD_))[t] = o;
    }
}

// ---------------------------------------------------------------------------
extern "C" void kernel_launch(void* const* d_in, const int* in_sizes, int n_in,
                              void* d_out, int out_size) {
    const float* x   = (const float*)d_in[0];   // (8,1024,256)
    const float* adj = (const float*)d_in[1];   // (8,1024,1024)
    const float* W   = (const float*)d_in[2];   // (256,256)
    const float* a   = (const float*)d_in[3];   // (1,4,128)
    float* out = (float*)d_out;

    float* Wx; cudaGetSymbolAddress((void**)&Wx, g_Wx);
    float* ei; cudaGetSymbolAddress((void**)&ei, g_ei);
    float* ej; cudaGetSymbolAddress((void**)&ej, g_ej);

    dim3 ggrid(B_ * N_ / 128, HD_ / 64);
    gemm_kernel<<<ggrid, 256>>>(x, W, Wx);
    eij_kernel<<<B_ * N_, 256>>>(a, Wx, ei, ej);
    gat_kernel<<<B_ * N_, 256>>>(adj, Wx, ei, ej, out);
}